// round 12
// baseline (speedup 1.0000x reference)
#include <cuda_runtime.h>
#include <cstdint>

#define B   32
#define H   384
#define W   640
#define C   128
#define HS  96      // H / SCALE
#define WS  160     // W / SCALE
#define FW  30
#define THRESH 0.015f
#define TOPK 2000
#define TBLOCKS 2048   // persistent transpose grid
#define PIX 4          // pixels per thread per swath in select
#define MAXCELLS 72    // slab budget: 72 cells * 512B = 36KB smem

// Static device scratch (allocation-free rule: __device__ globals allowed)
__device__ float d_hwc[(size_t)B * HS * WS * C];   // transposed featmap (only needed rows valid)
__device__ int   d_idx[B * TOPK];                  // selected linear pixel indices, -1 = invalid
__device__ int   d_ymin[B];                        // first needed feat row per batch
__device__ int   d_nrows[B];                       // number of needed feat rows per batch

// ---------------------------------------------------------------------------
// Kernel 1: ordered selection, swath-parallel (proven). One block per batch;
// swaths of 1024*PIX pixels; one block scan per swath; early exit at TOPK.
// ---------------------------------------------------------------------------
__global__ __launch_bounds__(1024) void select_kernel(
    const float* __restrict__ prob,
    const float* __restrict__ ratio,
    const int* __restrict__ rshape_raw,
    float* __restrict__ pts_out)
{
    const int b    = blockIdx.x;
    const int tid  = threadIdx.x;
    const int warp = tid >> 5;
    const int lane = tid & 31;

    __shared__ int sWarpBase[32];
    __shared__ int sTotal;
    __shared__ int sBase;
    __shared__ int sRmin, sRmax;
    if (tid == 0) { sBase = 0; sRmin = 0x7fffffff; sRmax = -1; }

    // r_shape dtype sniff: int64 LE -> word 1 is high half of first value (0);
    // int32 -> word 1 is W != 0.
    const int stride = (rshape_raw[1] == 0) ? 2 : 1;
    const int r0 = rshape_raw[(2 * b)     * stride];
    const int r1 = rshape_raw[(2 * b + 1) * stride];
    const int rowW     = r1 - 2 * FW;              // valid cols per row
    const int totalPix = (r0 - 2 * FW) * rowW;     // in-region pixel count
    const float rv = ratio[b];
    const float* pb = prob + (size_t)b * H * W;

    __syncthreads();

    for (int sw = 0; sw < totalPix; sw += 1024 * PIX) {
        const int pix0 = sw + PIX * tid;
        unsigned pmask = 0;
        int rr[PIX], cc[PIX];
        if (rowW > 0 && pix0 < totalPix) {
            const int rq = pix0 / rowW;
            int ri = FW + rq, ci = FW + pix0 - rq * rowW;
            #pragma unroll
            for (int j = 0; j < PIX; ++j) {
                rr[j] = ri; cc[j] = ci;
                if ((pix0 + j) < totalPix && pb[(size_t)ri * W + ci] > THRESH)
                    pmask |= (1u << j);
                if (++ci >= FW + rowW) { ci = FW; ++ri; }
            }
        }
        const int cnt = __popc(pmask);

        int incl = cnt;
        #pragma unroll
        for (int d = 1; d < 32; d <<= 1) {
            int y = __shfl_up_sync(0xffffffffu, incl, d);
            if (lane >= d) incl += y;
        }
        if (lane == 31) sWarpBase[warp] = incl;
        __syncthreads();
        if (tid < 32) {
            int v = sWarpBase[tid];
            int x = v;
            #pragma unroll
            for (int d = 1; d < 32; d <<= 1) {
                int y = __shfl_up_sync(0xffffffffu, x, d);
                if (tid >= d) x += y;
            }
            sWarpBase[tid] = x - v;
            if (tid == 31) sTotal = x;
        }
        __syncthreads();
        int pos = sBase + sWarpBase[warp] + (incl - cnt);

        int myRmin = 0x7fffffff, myRmax = -1;
        #pragma unroll
        for (int j = 0; j < PIX; ++j) {
            if (pmask & (1u << j)) {
                if (pos < TOPK) {
                    d_idx[b * TOPK + pos] = rr[j] * W + cc[j];
                    ((float2*)pts_out)[(size_t)b * TOPK + pos] =
                        make_float2((float)cc[j] / rv, (float)rr[j] / rv);
                    if (rr[j] < myRmin) myRmin = rr[j];
                    if (rr[j] > myRmax) myRmax = rr[j];
                }
                ++pos;
            }
        }
        if (myRmax >= 0) {
            atomicMin(&sRmin, myRmin);
            atomicMax(&sRmax, myRmax);
        }
        __syncthreads();
        if (tid == 0) sBase += sTotal;
        __syncthreads();
        if (sBase >= TOPK) break;
    }

    __syncthreads();
    {
        const int base = (sBase < TOPK) ? sBase : TOPK;
        for (int k = base + tid; k < TOPK; k += 1024) {
            d_idx[b * TOPK + k] = -1;
            ((float2*)pts_out)[(size_t)b * TOPK + k] = make_float2(0.0f, 0.0f);
        }
        if (tid == 0) {
            if (sRmax < 0) {
                d_ymin[b] = 0; d_nrows[b] = 0;
            } else {
                int ymin = sRmin >> 2;
                int ymax = (sRmax >> 2) + 1;
                if (ymax > HS - 1) ymax = HS - 1;
                d_ymin[b] = ymin;
                d_nrows[b] = ymax - ymin + 1;
            }
        }
    }
}

// ---------------------------------------------------------------------------
// Kernel 2: persistent CHW -> HWC transpose over a compact task list
// (proven). Task = (batch, feat row, tile); 20 tiles per row.
// ---------------------------------------------------------------------------
__global__ __launch_bounds__(256) void transpose_kernel(const float* __restrict__ feat)
{
    __shared__ int sOff[B + 1];
    __shared__ int sYmin[B];
    __shared__ float tile[32][33];

    const int t0 = threadIdx.y * 32 + threadIdx.x;
    if (t0 == 0) {
        int acc = 0;
        #pragma unroll
        for (int b = 0; b < B; ++b) {
            sOff[b] = acc;
            sYmin[b] = d_ymin[b];
            acc += d_nrows[b];
        }
        sOff[B] = acc;
    }
    __syncthreads();
    const int totalTasks = sOff[B] * 20;

    const int tx = threadIdx.x;  // 0..31
    const int ty = threadIdx.y;  // 0..7

    for (int t = blockIdx.x; t < totalTasks; t += TBLOCKS) {
        const int rowTask = t / 20;
        const int tileId  = t - rowTask * 20;
        int b = 0;
        while (sOff[b + 1] <= rowTask) ++b;        // uniform across block
        const int y  = sYmin[b] + (rowTask - sOff[b]);
        const int xt = tileId % 5;                 // 0..4 (x tiles of 32)
        const int ct = tileId / 5;                 // 0..3 (c tiles of 32)

        const float* src = feat + ((size_t)b * C) * (HS * WS) + (size_t)y * WS;
        #pragma unroll
        for (int i = 0; i < 4; ++i) {
            const int cc = ct * 32 + ty + i * 8;
            tile[ty + i * 8][tx] = src[(size_t)cc * (HS * WS) + xt * 32 + tx];
        }
        __syncthreads();
        float* dst = d_hwc + ((size_t)(b * HS + y) * WS) * C;
        #pragma unroll
        for (int i = 0; i < 4; ++i) {
            const int x = xt * 32 + ty + i * 8;
            dst[(size_t)x * C + ct * 32 + tx] = tile[tx][ty + i * 8];
        }
        __syncthreads();
    }
}

// ---------------------------------------------------------------------------
// Kernel 3: smem-slab bilinear gather.
// 256 threads = 8 warps x 32 channel-lanes; 64 consecutive points per block.
// Decode points -> bbox of needed coarse cells. If the bbox fits MAXCELLS,
// stage it from d_hwc into smem with ONE coalesced high-MLP burst (cells are
// contiguous in HWC), then compute from smem with register tap-dedup.
// Otherwise (row-wrap / sparse blocks) fall back to global dedup loads.
// ---------------------------------------------------------------------------
__global__ __launch_bounds__(256) void gather_kernel(float* __restrict__ des_out)
{
    const int b   = blockIdx.y;
    const int p0  = blockIdx.x * 64;
    const int tid = threadIdx.x;
    const int cg  = tid & 31;   // channel group (4 ch, float4)
    const int wp  = tid >> 5;   // warp 0..7 -> points wp*8 .. wp*8+7

    __shared__ float4 sSlab4[MAXCELLS * 32];   // 36 KB
    __shared__ float4 sWt[64];
    __shared__ int    sY[64], sX[64];
    __shared__ int    sBB[4];                  // ymin, ymax, xmin, xmax

    // ---- decode 64 points ----
    if (tid < 64) {
        const int p = p0 + tid;
        const int lin = (p < TOPK) ? d_idx[b * TOPK + p] : -1;
        int y0 = -1, x0 = 0;
        float4 wt = make_float4(0.f, 0.f, 0.f, 0.f);
        if (lin >= 0) {
            const int y = lin / W;
            const int x = lin - y * W;
            x0 = x >> 2;
            y0 = y >> 2;
            const float fx = (float)(x & 3) * 0.25f;
            const float fy = (float)(y & 3) * 0.25f;
            wt = make_float4((1.f - fx) * (1.f - fy),   // Ia (y0,x0)
                             (1.f - fx) * fy,           // Ib (y1,x0)
                             fx * (1.f - fy),           // Ic (y0,x1)
                             fx * fy);                  // Id (y1,x1)
        }
        sY[tid] = y0; sX[tid] = x0; sWt[tid] = wt;
    }
    __syncthreads();

    // ---- bbox of valid cells ----
    if (tid < 32) {
        int ymin = 0x7fffffff, ymax = -1, xmin = 0x7fffffff, xmax = -1;
        #pragma unroll
        for (int k = 0; k < 2; ++k) {
            const int j = tid + k * 32;
            const int yy = sY[j], xx = sX[j];
            if (yy >= 0) {
                ymin = min(ymin, yy); ymax = max(ymax, yy);
                xmin = min(xmin, xx); xmax = max(xmax, xx);
            }
        }
        #pragma unroll
        for (int d = 16; d > 0; d >>= 1) {
            ymin = min(ymin, __shfl_down_sync(0xffffffffu, ymin, d));
            ymax = max(ymax, __shfl_down_sync(0xffffffffu, ymax, d));
            xmin = min(xmin, __shfl_down_sync(0xffffffffu, xmin, d));
            xmax = max(xmax, __shfl_down_sync(0xffffffffu, xmax, d));
        }
        if (tid == 0) { sBB[0] = ymin; sBB[1] = ymax; sBB[2] = xmin; sBB[3] = xmax; }
    }
    __syncthreads();

    const int yMin = sBB[0], yMax = sBB[1], xMin = sBB[2], xMax = sBB[3];
    int slabCols = 0, nc = 0;
    bool useSlab = false;
    if (yMax >= 0) {
        const int slabRows = yMax - yMin + 2;   // +1 tap row
        slabCols = xMax - xMin + 2;             // +1 tap col
        nc = slabRows * slabCols;
        useSlab = (nc <= MAXCELLS);
    }

    const float4* hwc4 = (const float4*)d_hwc;

    // ---- stage slab (coalesced, one burst) ----
    if (useSlab) {
        for (int i = tid; i < nc * 32; i += 256) {
            const int cell = i >> 5;
            const int cgl  = i & 31;
            const int row  = cell / slabCols;
            const int col  = cell - row * slabCols;
            sSlab4[i] = hwc4[((size_t)(b * HS + yMin + row) * WS + xMin + col) * 32 + cgl];
        }
    }
    __syncthreads();

    // ---- compute: each warp walks 8 consecutive points with tap-dedup ----
    int cur = -1;
    float4 Ia = make_float4(0.f, 0.f, 0.f, 0.f), Ib = Ia, Ic = Ia, Id = Ia;
    const int jbase = wp * 8;

    #pragma unroll
    for (int i = 0; i < 8; ++i) {
        const int j = jbase + i;
        const int p = p0 + j;
        if (p >= TOPK) break;                 // warp-uniform
        const int yy = sY[j];                 // warp-uniform
        float4 v = make_float4(0.f, 0.f, 0.f, 0.f);
        if (yy >= 0) {
            if (useSlab) {
                const int rel = (yy - yMin) * slabCols + (sX[j] - xMin);
                if (rel != cur) {             // warp-uniform branch
                    const float4* s4 = sSlab4 + rel * 32 + cg;
                    Ia = s4[0];
                    Ic = s4[32];
                    Ib = s4[slabCols * 32];
                    Id = s4[slabCols * 32 + 32];
                    cur = rel;
                }
            } else {
                const int off = ((b * HS + yy) * WS + sX[j]) * 32;
                if (off != cur) {
                    const float4* basep = hwc4 + off + cg;
                    Ia = basep[0];
                    Ic = basep[32];
                    Ib = basep[WS * 32];
                    Id = basep[WS * 32 + 32];
                    cur = off;
                }
            }
            const float4 w = sWt[j];
            v.x = Ia.x * w.x + Ib.x * w.y + Ic.x * w.z + Id.x * w.w;
            v.y = Ia.y * w.x + Ib.y * w.y + Ic.y * w.z + Id.y * w.w;
            v.z = Ia.z * w.x + Ib.z * w.y + Ic.z * w.z + Id.z * w.w;
            v.w = Ia.w * w.x + Ib.w * w.y + Ic.w * w.z + Id.w * w.w;
        }
        ((float4*)des_out)[((size_t)b * TOPK + p) * 32 + cg] = v;
    }
}

// ---------------------------------------------------------------------------
extern "C" void kernel_launch(void* const* d_in, const int* in_sizes, int n_in,
                              void* d_out, int out_size)
{
    const float* prob   = (const float*)d_in[0];      // [B,1,H,W]
    const float* feat   = (const float*)d_in[1];      // [B,C,HS,WS]
    const float* ratio  = (const float*)d_in[2];      // [B,1]
    const int*   rshape = (const int*)d_in[3];        // [B,2] int32 (or int64-packed)

    float* pts_out = (float*)d_out;                        // [B,TOPK,2]
    float* des_out = (float*)d_out + (size_t)B * TOPK * 2; // [B,TOPK,C]

    select_kernel<<<B, 1024>>>(prob, ratio, rshape, pts_out);
    transpose_kernel<<<TBLOCKS, dim3(32, 8)>>>(feat);
    gather_kernel<<<dim3((TOPK + 63) / 64, B), 256>>>(des_out);
}